// round 16
// baseline (speedup 1.0000x reference)
#include <cuda_runtime.h>
#include <cuda_fp16.h>
#include <cstdint>

// Fused edge-MLP on HMMA (mma.sync m16n8k16 fp16, fp32 accum), single-term:
//   x = [e | h[src]+h[dst]]  [E,256] -> 3x (leaky o linear) -> out [E,128]
// A and W both rounded to fp16 (fp32 accumulate): est. rel err ~5e-4 (<1e-3).
//
// CTA = 256 threads (8 warps), 4 passes of 256 edges (1024 edges/CTA).
// Each warp owns 32 edges = 2 m16 groups x all 128 outputs (2x16 accum tiles).
// One W LDS.128 feeds 4 MMAs (2 m-groups x 2 paired j-tiles). All W fragments
// (128 KB) staged to smem once; no barriers in the pass loop. Activations stay
// in registers across layers (C m16n8 == A m16k8 halves).

#define NT     256
#define DD     128
#define EPW    32          // edges per warp
#define CTA_E  256         // edges per pass (8 warps * 32)
#define PASSES 4

// Paired W fragment image: [gk (0..31)][jp (0..7)][lane (0..31)] -> uint4
//   uint4 = {b0(j=2jp), b1(j=2jp), b0(j=2jp+1), b1(j=2jp+1)}  (fp16x2 words)
//   gk 0..15 : layer1 ksteps (K=256), gk 16..23 : layer2, gk 24..31 : layer3
__device__ __align__(16) uint4 g_wfrag4[32 * 8 * 32];   // 128 KB

__device__ __forceinline__ uint32_t pack_h2(__half a, __half b) {
    __half2 t;
    t.x = a; t.y = b;
    return *(uint32_t*)&t;
}
__device__ __forceinline__ uint32_t pack_f2(float x, float y) {
    return pack_h2(__float2half_rn(x), __float2half_rn(y));
}
__device__ __forceinline__ float leaky(float v) { return v >= 0.f ? v : 0.01f * v; }

__device__ __forceinline__ void mma_f16(float c[4], const uint32_t a[4],
                                        uint32_t b0, uint32_t b1) {
    asm volatile(
        "mma.sync.aligned.m16n8k16.row.col.f32.f16.f16.f32 "
        "{%0,%1,%2,%3}, {%4,%5,%6,%7}, {%8,%9}, {%0,%1,%2,%3};"
        : "+f"(c[0]), "+f"(c[1]), "+f"(c[2]), "+f"(c[3])
        : "r"(a[0]), "r"(a[1]), "r"(a[2]), "r"(a[3]), "r"(b0), "r"(b1));
}

// ---- kernel 0: build paired per-lane W fragment image (one-time, tiny) ----
__global__ void build_wfrag(const float* __restrict__ W1,
                            const float* __restrict__ W2,
                            const float* __restrict__ W3) {
    int idx = blockIdx.x * blockDim.x + threadIdx.x;
    if (idx >= 32 * 16 * 32) return;
    int lane = idx & 31;
    int j    = (idx >> 5) & 15;
    int gk   = idx >> 9;
    const float* W; int Kin, kk;
    if (gk < 16)      { W = W1; Kin = 256; kk = gk; }
    else if (gk < 24) { W = W2; Kin = 128; kk = gk - 16; }
    else              { W = W3; Kin = 128; kk = gk - 24; }
    int g = lane >> 2, t = lane & 3;
    int n = 8 * j + g;
    int K0 = 16 * kk;
    const float* r = W + (size_t)n * Kin + K0;
    uint2 o;
    o.x = pack_f2(r[2 * t],     r[2 * t + 1]);
    o.y = pack_f2(r[2 * t + 8], r[2 * t + 9]);
    uint2* dst = (uint2*)g_wfrag4;
    dst[(((size_t)gk * 8 + (j >> 1)) * 32 + lane) * 2 + (j & 1)] = o;
}

// ---- one k16 step: 2 m-groups x 16 n-tiles; 1 LDS.128 per 4 MMAs ----
__device__ __forceinline__ void kstep2(float acc[2][16][4],
                                       const uint32_t a0[4], const uint32_t a1[4],
                                       const uint4* w4, int lane) {
#pragma unroll
    for (int jp = 0; jp < 8; ++jp) {
        uint4 wv = w4[jp * 32 + lane];
        mma_f16(acc[0][2 * jp],     a0, wv.x, wv.y);
        mma_f16(acc[0][2 * jp + 1], a0, wv.z, wv.w);
        mma_f16(acc[1][2 * jp],     a1, wv.x, wv.y);
        mma_f16(acc[1][2 * jp + 1], a1, wv.z, wv.w);
    }
}

__device__ __forceinline__ void bias_act(float acc[16][4], const float* sbias,
                                         int t) {
#pragma unroll
    for (int j = 0; j < 16; ++j) {
        float2 b = *(const float2*)(sbias + 8 * j + 2 * t);
        acc[j][0] = leaky(acc[j][0] + b.x);
        acc[j][1] = leaky(acc[j][1] + b.y);
        acc[j][2] = leaky(acc[j][2] + b.x);
        acc[j][3] = leaky(acc[j][3] + b.y);
    }
}

// C tiles -> next-layer A fragments (single fp16; layouts match).
__device__ __forceinline__ void c_to_a(const float acc[16][4], uint32_t af[8][4]) {
#pragma unroll
    for (int kk = 0; kk < 8; ++kk) {
        const float* c0 = acc[2 * kk];
        const float* c1 = acc[2 * kk + 1];
        af[kk][0] = pack_f2(c0[0], c0[1]);
        af[kk][1] = pack_f2(c0[2], c0[3]);
        af[kk][2] = pack_f2(c1[0], c1[1]);
        af[kk][3] = pack_f2(c1[2], c1[3]);
    }
}

__global__ __launch_bounds__(NT, 1)
void edge_mlp_hmma(const float* __restrict__ e_in, const float* __restrict__ h,
                   const int* __restrict__ src, const int* __restrict__ dst,
                   const float* __restrict__ b1, const float* __restrict__ b2,
                   const float* __restrict__ b3, float* __restrict__ out,
                   int E) {
    extern __shared__ unsigned char smraw[];
    uint4* wsm   = (uint4*)smraw;                 // 8192 uint4 = 128 KB
    float* sbias = (float*)(smraw + 131072);      // 3 x 128 floats

    const int tid  = threadIdx.x;
    const int lane = tid & 31;
    const int w    = tid >> 5;
    const int g    = lane >> 2;
    const int t    = lane & 3;

    // ---- stage ALL weight fragments + biases once ----
#pragma unroll
    for (int i = 0; i < 32; ++i) wsm[tid + i * NT] = g_wfrag4[tid + i * NT];
    if (tid < DD) {
        sbias[tid]           = b1[tid];
        sbias[DD + tid]      = b2[tid];
        sbias[2 * DD + tid]  = b3[tid];
    }
    __syncthreads();
    // No barriers below: warps pipeline independently.

    for (int pass = 0; pass < PASSES; ++pass) {
        const int base = (blockIdx.x * PASSES + pass) * CTA_E;
        if (base >= E) break;
        // 4 edge rows per lane: m-group 0 = {e0, e1}, m-group 1 = {e2, e3}
        const int e0 = base + EPW * w + g;
        const int e1 = e0 + 8;
        const int e2 = e0 + 16;
        const int e3 = e0 + 24;
        const bool v0 = e0 < E, v1 = e1 < E, v2 = e2 < E, v3 = e3 < E;
        const int si0 = v0 ? src[e0] : 0, di0 = v0 ? dst[e0] : 0;
        const int si1 = v1 ? src[e1] : 0, di1 = v1 ? dst[e1] : 0;
        const int si2 = v2 ? src[e2] : 0, di2 = v2 ? dst[e2] : 0;
        const int si3 = v3 ? src[e3] : 0, di3 = v3 ? dst[e3] : 0;

        float acc[2][16][4];
#pragma unroll
        for (int m = 0; m < 2; ++m)
#pragma unroll
            for (int j = 0; j < 16; ++j)
                acc[m][j][0] = acc[m][j][1] = acc[m][j][2] = acc[m][j][3] = 0.f;

        // ---------- layer 1, chunk 0: e part (x cols 0..127) ----------
#pragma unroll
        for (int kk = 0; kk < 8; ++kk) {
            const int K0 = 16 * kk;
            float2 z = make_float2(0.f, 0.f);
            float2 q0 = v0 ? *(const float2*)(e_in + (size_t)e0 * DD + K0 + 2 * t)     : z;
            float2 q1 = v1 ? *(const float2*)(e_in + (size_t)e1 * DD + K0 + 2 * t)     : z;
            float2 q2 = v0 ? *(const float2*)(e_in + (size_t)e0 * DD + K0 + 2 * t + 8) : z;
            float2 q3 = v1 ? *(const float2*)(e_in + (size_t)e1 * DD + K0 + 2 * t + 8) : z;
            float2 r0 = v2 ? *(const float2*)(e_in + (size_t)e2 * DD + K0 + 2 * t)     : z;
            float2 r1 = v3 ? *(const float2*)(e_in + (size_t)e3 * DD + K0 + 2 * t)     : z;
            float2 r2 = v2 ? *(const float2*)(e_in + (size_t)e2 * DD + K0 + 2 * t + 8) : z;
            float2 r3 = v3 ? *(const float2*)(e_in + (size_t)e3 * DD + K0 + 2 * t + 8) : z;
            uint32_t a0[4], a1[4];
            a0[0] = pack_f2(q0.x, q0.y); a0[1] = pack_f2(q1.x, q1.y);
            a0[2] = pack_f2(q2.x, q2.y); a0[3] = pack_f2(q3.x, q3.y);
            a1[0] = pack_f2(r0.x, r0.y); a1[1] = pack_f2(r1.x, r1.y);
            a1[2] = pack_f2(r2.x, r2.y); a1[3] = pack_f2(r3.x, r3.y);
            kstep2(acc, a0, a1, wsm + kk * 8 * 32, lane);
        }

        // ---------- layer 1, chunk 1: h-sum part (x cols 128..255) ----------
#pragma unroll
        for (int kk = 0; kk < 8; ++kk) {
            const int K0 = 16 * kk;
            uint32_t a0[4], a1[4];
            {
                float2 z = make_float2(0.f, 0.f);
                float2 p0 = z, p1 = z, p2 = z, p3 = z;
                if (v0) {
                    float2 a = *(const float2*)(h + (size_t)si0 * DD + K0 + 2 * t);
                    float2 b = *(const float2*)(h + (size_t)di0 * DD + K0 + 2 * t);
                    p0 = make_float2(a.x + b.x, a.y + b.y);
                    a = *(const float2*)(h + (size_t)si0 * DD + K0 + 2 * t + 8);
                    b = *(const float2*)(h + (size_t)di0 * DD + K0 + 2 * t + 8);
                    p2 = make_float2(a.x + b.x, a.y + b.y);
                }
                if (v1) {
                    float2 a = *(const float2*)(h + (size_t)si1 * DD + K0 + 2 * t);
                    float2 b = *(const float2*)(h + (size_t)di1 * DD + K0 + 2 * t);
                    p1 = make_float2(a.x + b.x, a.y + b.y);
                    a = *(const float2*)(h + (size_t)si1 * DD + K0 + 2 * t + 8);
                    b = *(const float2*)(h + (size_t)di1 * DD + K0 + 2 * t + 8);
                    p3 = make_float2(a.x + b.x, a.y + b.y);
                }
                a0[0] = pack_f2(p0.x, p0.y); a0[1] = pack_f2(p1.x, p1.y);
                a0[2] = pack_f2(p2.x, p2.y); a0[3] = pack_f2(p3.x, p3.y);
            }
            {
                float2 z = make_float2(0.f, 0.f);
                float2 p0 = z, p1 = z, p2 = z, p3 = z;
                if (v2) {
                    float2 a = *(const float2*)(h + (size_t)si2 * DD + K0 + 2 * t);
                    float2 b = *(const float2*)(h + (size_t)di2 * DD + K0 + 2 * t);
                    p0 = make_float2(a.x + b.x, a.y + b.y);
                    a = *(const float2*)(h + (size_t)si2 * DD + K0 + 2 * t + 8);
                    b = *(const float2*)(h + (size_t)di2 * DD + K0 + 2 * t + 8);
                    p2 = make_float2(a.x + b.x, a.y + b.y);
                }
                if (v3) {
                    float2 a = *(const float2*)(h + (size_t)si3 * DD + K0 + 2 * t);
                    float2 b = *(const float2*)(h + (size_t)di3 * DD + K0 + 2 * t);
                    p1 = make_float2(a.x + b.x, a.y + b.y);
                    a = *(const float2*)(h + (size_t)si3 * DD + K0 + 2 * t + 8);
                    b = *(const float2*)(h + (size_t)di3 * DD + K0 + 2 * t + 8);
                    p3 = make_float2(a.x + b.x, a.y + b.y);
                }
                a1[0] = pack_f2(p0.x, p0.y); a1[1] = pack_f2(p1.x, p1.y);
                a1[2] = pack_f2(p2.x, p2.y); a1[3] = pack_f2(p3.x, p3.y);
            }
            kstep2(acc, a0, a1, wsm + (8 + kk) * 8 * 32, lane);
        }

        // ---------- epilogue 1 -> register A fragments ----------
        uint32_t af[2][8][4];
#pragma unroll
        for (int m = 0; m < 2; ++m) {
            bias_act(acc[m], sbias, t);
            c_to_a(acc[m], af[m]);
#pragma unroll
            for (int j = 0; j < 16; ++j)
                acc[m][j][0] = acc[m][j][1] = acc[m][j][2] = acc[m][j][3] = 0.f;
        }

        // ---------- layer 2 (frags at uint4 offset 4096) ----------
#pragma unroll
        for (int kk = 0; kk < 8; ++kk)
            kstep2(acc, af[0][kk], af[1][kk], wsm + 4096 + kk * 8 * 32, lane);

#pragma unroll
        for (int m = 0; m < 2; ++m) {
            bias_act(acc[m], sbias + DD, t);
            c_to_a(acc[m], af[m]);
#pragma unroll
            for (int j = 0; j < 16; ++j)
                acc[m][j][0] = acc[m][j][1] = acc[m][j][2] = acc[m][j][3] = 0.f;
        }

        // ---------- layer 3 (frags at uint4 offset 6144) ----------
#pragma unroll
        for (int kk = 0; kk < 8; ++kk)
            kstep2(acc, af[0][kk], af[1][kk], wsm + 6144 + kk * 8 * 32, lane);

        // ---------- final epilogue: bias + leaky + coalesced float2 stores ----
        const float* sb3 = sbias + 2 * DD;
#pragma unroll
        for (int m = 0; m < 2; ++m) {
            const int ea = m ? e2 : e0;
            const int eb = m ? e3 : e1;
            const bool va = m ? v2 : v0;
            const bool vb = m ? v3 : v1;
#pragma unroll
            for (int j = 0; j < 16; ++j) {
                float2 b = *(const float2*)(sb3 + 8 * j + 2 * t);
                float c0 = leaky(acc[m][j][0] + b.x);
                float c1 = leaky(acc[m][j][1] + b.y);
                float c2 = leaky(acc[m][j][2] + b.x);
                float c3 = leaky(acc[m][j][3] + b.y);
                if (va) *(float2*)(out + (size_t)ea * DD + 8 * j + 2 * t) = make_float2(c0, c1);
                if (vb) *(float2*)(out + (size_t)eb * DD + 8 * j + 2 * t) = make_float2(c2, c3);
            }
        }
    }
}

extern "C" void kernel_launch(void* const* d_in, const int* in_sizes, int n_in,
                              void* d_out, int out_size) {
    const float* e_in = (const float*)d_in[0];
    const float* h    = (const float*)d_in[1];
    const int*   src  = (const int*)d_in[2];
    const int*   dst  = (const int*)d_in[3];
    const float* W1   = (const float*)d_in[4];
    const float* b1   = (const float*)d_in[5];
    const float* W2   = (const float*)d_in[6];
    const float* b2   = (const float*)d_in[7];
    const float* W3   = (const float*)d_in[8];
    const float* b3   = (const float*)d_in[9];
    float* out = (float*)d_out;

    const int E = in_sizes[0] / DD;
    const int smem_dyn = 131072 + 3 * DD * (int)sizeof(float);

    cudaFuncSetAttribute(edge_mlp_hmma,
                         cudaFuncAttributeMaxDynamicSharedMemorySize, smem_dyn);

    build_wfrag<<<(32 * 16 * 32 + 255) / 256, 256>>>(W1, W2, W3);

    const int edges_per_cta = CTA_E * PASSES;
    const int grid = (E + edges_per_cta - 1) / edges_per_cta;
    edge_mlp_hmma<<<grid, NT, smem_dyn>>>(e_in, h, src, dst, b1, b2, b3, out, E);
}

// round 17
// speedup vs baseline: 1.4192x; 1.4192x over previous
#include <cuda_runtime.h>
#include <cuda_fp16.h>
#include <cstdint>

// Fused edge-MLP on HMMA (mma.sync m16n8k16 fp16, fp32 accum), single-term:
//   x = [e | h[src]+h[dst]]  [E,256] -> 3x (leaky o linear) -> out [E,128]
// A and W both rounded to fp16 (fp32 accumulate): measured rel err ~4.9e-4.
//
// CTA = 256 threads (8 warps), 4 tiles of 128 edges (512 edges/CTA... 4x128).
// Each warp owns 16 edges x all 128 outputs = 16 m16n8 accum tiles (64 regs).
// One W LDS.128 feeds 2 MMAs (paired j-tiles). All W fragments (128 KB) staged
// to smem once; no barriers in the tile loop. Activations stay in registers
// across layers (C m16n8 == A m16k8 halves).

#define NT     256
#define TILE_M 128
#define DD     128
#define TILES_PER_CTA 4

// Paired W fragment image: [gk (0..31)][jp (0..7)][lane (0..31)] -> uint4
//   uint4 = {b0(j=2jp), b1(j=2jp), b0(j=2jp+1), b1(j=2jp+1)}  (fp16x2 words)
//   gk 0..15 : layer1 ksteps (K=256), gk 16..23 : layer2, gk 24..31 : layer3
__device__ __align__(16) uint4 g_wfrag4[32 * 8 * 32];   // 128 KB

__device__ __forceinline__ uint32_t pack_h2(__half a, __half b) {
    __half2 t;
    t.x = a; t.y = b;
    return *(uint32_t*)&t;
}
__device__ __forceinline__ uint32_t pack_f2(float x, float y) {
    return pack_h2(__float2half_rn(x), __float2half_rn(y));
}
__device__ __forceinline__ float leaky(float v) { return v >= 0.f ? v : 0.01f * v; }

__device__ __forceinline__ void mma_f16(float c[4], const uint32_t a[4],
                                        uint32_t b0, uint32_t b1) {
    asm volatile(
        "mma.sync.aligned.m16n8k16.row.col.f32.f16.f16.f32 "
        "{%0,%1,%2,%3}, {%4,%5,%6,%7}, {%8,%9}, {%0,%1,%2,%3};"
        : "+f"(c[0]), "+f"(c[1]), "+f"(c[2]), "+f"(c[3])
        : "r"(a[0]), "r"(a[1]), "r"(a[2]), "r"(a[3]), "r"(b0), "r"(b1));
}

// ---- kernel 0: build paired per-lane W fragment image (one-time, tiny) ----
__global__ void build_wfrag(const float* __restrict__ W1,
                            const float* __restrict__ W2,
                            const float* __restrict__ W3) {
    int idx = blockIdx.x * blockDim.x + threadIdx.x;
    if (idx >= 32 * 16 * 32) return;
    int lane = idx & 31;
    int j    = (idx >> 5) & 15;
    int gk   = idx >> 9;
    const float* W; int Kin, kk;
    if (gk < 16)      { W = W1; Kin = 256; kk = gk; }
    else if (gk < 24) { W = W2; Kin = 128; kk = gk - 16; }
    else              { W = W3; Kin = 128; kk = gk - 24; }
    int g = lane >> 2, t = lane & 3;
    int n = 8 * j + g;
    int K0 = 16 * kk;
    const float* r = W + (size_t)n * Kin + K0;
    uint2 o;
    o.x = pack_f2(r[2 * t],     r[2 * t + 1]);
    o.y = pack_f2(r[2 * t + 8], r[2 * t + 9]);
    uint2* dst = (uint2*)g_wfrag4;
    dst[(((size_t)gk * 8 + (j >> 1)) * 32 + lane) * 2 + (j & 1)] = o;
}

// ---- one k16 step over 16 n-tiles: 1 LDS.128 per 2 MMAs ----
__device__ __forceinline__ void kstep(float acc[16][4], const uint32_t a[4],
                                      const uint4* w4, int lane) {
#pragma unroll
    for (int jp = 0; jp < 8; ++jp) {
        uint4 wv = w4[jp * 32 + lane];
        mma_f16(acc[2 * jp],     a, wv.x, wv.y);
        mma_f16(acc[2 * jp + 1], a, wv.z, wv.w);
    }
}

__device__ __forceinline__ void bias_act(float acc[16][4], const float* sbias,
                                         int t) {
#pragma unroll
    for (int j = 0; j < 16; ++j) {
        float2 b = *(const float2*)(sbias + 8 * j + 2 * t);
        acc[j][0] = leaky(acc[j][0] + b.x);
        acc[j][1] = leaky(acc[j][1] + b.y);
        acc[j][2] = leaky(acc[j][2] + b.x);
        acc[j][3] = leaky(acc[j][3] + b.y);
    }
}

// C tiles -> next-layer A fragments (single fp16; layouts match).
__device__ __forceinline__ void c_to_a(const float acc[16][4], uint32_t af[8][4]) {
#pragma unroll
    for (int kk = 0; kk < 8; ++kk) {
        const float* c0 = acc[2 * kk];
        const float* c1 = acc[2 * kk + 1];
        af[kk][0] = pack_f2(c0[0], c0[1]);
        af[kk][1] = pack_f2(c0[2], c0[3]);
        af[kk][2] = pack_f2(c1[0], c1[1]);
        af[kk][3] = pack_f2(c1[2], c1[3]);
    }
}

__global__ __launch_bounds__(NT, 1)
void edge_mlp_hmma(const float* __restrict__ e_in, const float* __restrict__ h,
                   const int* __restrict__ src, const int* __restrict__ dst,
                   const float* __restrict__ b1, const float* __restrict__ b2,
                   const float* __restrict__ b3, float* __restrict__ out,
                   int E) {
    extern __shared__ unsigned char smraw[];
    uint4* wsm   = (uint4*)smraw;                 // 8192 uint4 = 128 KB
    float* sbias = (float*)(smraw + 131072);      // 3 x 128 floats

    const int tid  = threadIdx.x;
    const int lane = tid & 31;
    const int w    = tid >> 5;
    const int g    = lane >> 2;
    const int t    = lane & 3;

    // ---- stage ALL weight fragments + biases once ----
#pragma unroll
    for (int i = 0; i < 32; ++i) wsm[tid + i * NT] = g_wfrag4[tid + i * NT];
    if (tid < DD) {
        sbias[tid]           = b1[tid];
        sbias[DD + tid]      = b2[tid];
        sbias[2 * DD + tid]  = b3[tid];
    }
    __syncthreads();
    // No barriers below: warps pipeline independently.

    for (int tile = 0; tile < TILES_PER_CTA; ++tile) {
        const int base = (blockIdx.x * TILES_PER_CTA + tile) * TILE_M;
        if (base >= E) break;
        const int e0 = base + 16 * w + g;
        const int e1 = e0 + 8;
        const bool v0 = e0 < E, v1 = e1 < E;
        const int si0 = v0 ? src[e0] : 0, di0 = v0 ? dst[e0] : 0;
        const int si1 = v1 ? src[e1] : 0, di1 = v1 ? dst[e1] : 0;

        float acc[16][4];
#pragma unroll
        for (int j = 0; j < 16; ++j)
            acc[j][0] = acc[j][1] = acc[j][2] = acc[j][3] = 0.f;

        // ---------- layer 1, chunk 0: e part (x cols 0..127) ----------
#pragma unroll
        for (int kk = 0; kk < 8; ++kk) {
            const int K0 = 16 * kk;
            float2 z = make_float2(0.f, 0.f);
            float2 p0 = v0 ? *(const float2*)(e_in + (size_t)e0 * DD + K0 + 2 * t)     : z;
            float2 p1 = v1 ? *(const float2*)(e_in + (size_t)e1 * DD + K0 + 2 * t)     : z;
            float2 p2 = v0 ? *(const float2*)(e_in + (size_t)e0 * DD + K0 + 2 * t + 8) : z;
            float2 p3 = v1 ? *(const float2*)(e_in + (size_t)e1 * DD + K0 + 2 * t + 8) : z;
            uint32_t a[4];
            a[0] = pack_f2(p0.x, p0.y);
            a[1] = pack_f2(p1.x, p1.y);
            a[2] = pack_f2(p2.x, p2.y);
            a[3] = pack_f2(p3.x, p3.y);
            kstep(acc, a, wsm + kk * 8 * 32, lane);
        }

        // ---------- layer 1, chunk 1: h-sum part (x cols 128..255) ----------
#pragma unroll
        for (int kk = 0; kk < 8; ++kk) {
            const int K0 = 16 * kk;
            float2 z = make_float2(0.f, 0.f);
            float2 p0 = z, p1 = z, p2 = z, p3 = z;
            if (v0) {
                float2 a = *(const float2*)(h + (size_t)si0 * DD + K0 + 2 * t);
                float2 b = *(const float2*)(h + (size_t)di0 * DD + K0 + 2 * t);
                p0 = make_float2(a.x + b.x, a.y + b.y);
                a = *(const float2*)(h + (size_t)si0 * DD + K0 + 2 * t + 8);
                b = *(const float2*)(h + (size_t)di0 * DD + K0 + 2 * t + 8);
                p2 = make_float2(a.x + b.x, a.y + b.y);
            }
            if (v1) {
                float2 a = *(const float2*)(h + (size_t)si1 * DD + K0 + 2 * t);
                float2 b = *(const float2*)(h + (size_t)di1 * DD + K0 + 2 * t);
                p1 = make_float2(a.x + b.x, a.y + b.y);
                a = *(const float2*)(h + (size_t)si1 * DD + K0 + 2 * t + 8);
                b = *(const float2*)(h + (size_t)di1 * DD + K0 + 2 * t + 8);
                p3 = make_float2(a.x + b.x, a.y + b.y);
            }
            uint32_t a[4];
            a[0] = pack_f2(p0.x, p0.y);
            a[1] = pack_f2(p1.x, p1.y);
            a[2] = pack_f2(p2.x, p2.y);
            a[3] = pack_f2(p3.x, p3.y);
            kstep(acc, a, wsm + (8 + kk) * 8 * 32, lane);
        }

        // ---------- epilogue 1 -> register A fragments ----------
        uint32_t af[8][4];
        bias_act(acc, sbias, t);
        c_to_a(acc, af);
#pragma unroll
        for (int j = 0; j < 16; ++j)
            acc[j][0] = acc[j][1] = acc[j][2] = acc[j][3] = 0.f;

        // ---------- layer 2 (frags at uint4 offset 4096) ----------
#pragma unroll
        for (int kk = 0; kk < 8; ++kk)
            kstep(acc, af[kk], wsm + 4096 + kk * 8 * 32, lane);

        bias_act(acc, sbias + DD, t);
        c_to_a(acc, af);
#pragma unroll
        for (int j = 0; j < 16; ++j)
            acc[j][0] = acc[j][1] = acc[j][2] = acc[j][3] = 0.f;

        // ---------- layer 3 (frags at uint4 offset 6144) ----------
#pragma unroll
        for (int kk = 0; kk < 8; ++kk)
            kstep(acc, af[kk], wsm + 6144 + kk * 8 * 32, lane);

        // ---------- final epilogue: bias + leaky + coalesced float2 stores ----
        const float* sb3 = sbias + 2 * DD;
#pragma unroll
        for (int j = 0; j < 16; ++j) {
            float2 b = *(const float2*)(sb3 + 8 * j + 2 * t);
            float c0 = leaky(acc[j][0] + b.x);
            float c1 = leaky(acc[j][1] + b.y);
            float c2 = leaky(acc[j][2] + b.x);
            float c3 = leaky(acc[j][3] + b.y);
            if (v0) *(float2*)(out + (size_t)e0 * DD + 8 * j + 2 * t) = make_float2(c0, c1);
            if (v1) *(float2*)(out + (size_t)e1 * DD + 8 * j + 2 * t) = make_float2(c2, c3);
        }
    }
}

extern "C" void kernel_launch(void* const* d_in, const int* in_sizes, int n_in,
                              void* d_out, int out_size) {
    const float* e_in = (const float*)d_in[0];
    const float* h    = (const float*)d_in[1];
    const int*   src  = (const int*)d_in[2];
    const int*   dst  = (const int*)d_in[3];
    const float* W1   = (const float*)d_in[4];
    const float* b1   = (const float*)d_in[5];
    const float* W2   = (const float*)d_in[6];
    const float* b2   = (const float*)d_in[7];
    const float* W3   = (const float*)d_in[8];
    const float* b3   = (const float*)d_in[9];
    float* out = (float*)d_out;

    const int E = in_sizes[0] / DD;
    const int smem_dyn = 131072 + 3 * DD * (int)sizeof(float);

    cudaFuncSetAttribute(edge_mlp_hmma,
                         cudaFuncAttributeMaxDynamicSharedMemorySize, smem_dyn);

    build_wfrag<<<(32 * 16 * 32 + 255) / 256, 256>>>(W1, W2, W3);

    const int edges_per_cta = TILE_M * TILES_PER_CTA;
    const int grid = (E + edges_per_cta - 1) / edges_per_cta;
    edge_mlp_hmma<<<grid, NT, smem_dyn>>>(e_in, h, src, dst, b1, b2, b3, out, E);
}